// round 12
// baseline (speedup 1.0000x reference)
#include <cuda_runtime.h>
#include <cuda_bf16.h>

#define B_ 128
#define H_ 512
#define HG_ 2048
#define T_ 512
#define FIN 64
#define FOUT 8
#define WOUT 64
#define NCTA 128
#define NTHR 512
#define NTOT (NCTA*NTHR)
#define SRED_BYTES (8*2304*4)   // 73728

// W: [(ntile*NK16+k16)*32+lane] = {b0h,b1h,b0l,b1l}
// A-type: per (mtile,k16): 64 uint4 = hi[0..31] | lo[32..63]
__device__ __align__(16) uint4 gWp[6][524288];   // set3 = composed dec-l0 (NK16=64)
__device__ __align__(16) uint4 gWp0d[270336];    // original dec-l0 (NK16=33)
__device__ __align__(16) uint4 gXp[1048576];
__device__ __align__(16) uint4 gPh[2][3][16384];
__device__ __align__(16) uint4 gPp[512];
__device__ float gBias[7][HG_];                  // [6] = composed dec-l0 bias
__device__ float g_h[3][B_][H_];
__device__ float g_c[3][B_][H_];
__device__ unsigned g_cnt = 0;
__device__ volatile unsigned g_gen = 0;
__device__ unsigned g_cnt4[4*32];
__device__ volatile unsigned g_gen4[4*32];

__device__ __forceinline__ float sigmoidf_(float x){ return 1.f/(1.f+expf(-x)); }
__device__ __forceinline__ void bsplit(float v, unsigned short& h, unsigned short& l){
    __nv_bfloat16 bh = __float2bfloat16(v);
    __nv_bfloat16 bl = __float2bfloat16(v - __bfloat162float(bh));
    h = __bfloat16_as_ushort(bh); l = __bfloat16_as_ushort(bl);
}
__device__ __forceinline__ unsigned packu(unsigned short e, unsigned short o){
    return (unsigned)e | ((unsigned)o << 16);
}
__device__ __forceinline__ void grid_barrier(){
    __syncthreads();
    if (threadIdx.x == 0){
        __threadfence();
        unsigned gen = g_gen;
        if (atomicAdd(&g_cnt,1u) == NCTA-1){ g_cnt = 0; __threadfence(); g_gen = gen+1; }
        else { while (g_gen == gen) {} }
        __threadfence();
    }
    __syncthreads();
}
__device__ __forceinline__ void group_barrier(int grp){
    __syncthreads();
    if (threadIdx.x == 0){
        __threadfence();
        unsigned* cnt = &g_cnt4[grp*32];
        volatile unsigned* gen = &g_gen4[grp*32];
        unsigned gv = *gen;
        if (atomicAdd(cnt,1u) == 31){ *cnt = 0; __threadfence(); *gen = gv+1; }
        else { while (*gen == gv) {} }
        __threadfence();
    }
    __syncthreads();
}
__device__ __forceinline__ void mma_bf16(float* d, const uint4 a, unsigned b0, unsigned b1){
    asm volatile("mma.sync.aligned.m16n8k16.row.col.f32.bf16.bf16.f32 "
        "{%0,%1,%2,%3}, {%4,%5,%6,%7}, {%8,%9}, {%0,%1,%2,%3};"
        : "+f"(d[0]), "+f"(d[1]), "+f"(d[2]), "+f"(d[3])
        : "r"(a.x), "r"(a.y), "r"(a.z), "r"(a.w), "r"(b0), "r"(b1));
}
__device__ __forceinline__ void cell_scatter(
    int l, int b, int j, float g0, float g1, float g2, float g3,
    uint4* pHw, bool wr_gh)
{
    float co = g_c[l][b][j];
    float cn = sigmoidf_(g1)*co + sigmoidf_(g0)*tanhf(g2);
    g_c[l][b][j] = cn;
    float hv = sigmoidf_(g3)*tanhf(cn);
    if (wr_gh) g_h[l][b][j] = hv;
    unsigned short hs, ls; bsplit(hv, hs, ls);
    int mt = b>>4, rb = b&15, gg = rb&7, a01 = rb>>3;
    int k16 = j>>4, kr = j&15, tg = (kr>>1)&3, r24 = kr>>3, half = kr&1;
    int regidx = a01 + (r24<<1);
    unsigned short* dst = (unsigned short*)(pHw + (size_t)(mt*32 + k16)*64 + (gg*4 + tg));
    dst[regidx*2 + half] = hs;
    dst[256 + regidx*2 + half] = ls;
}

// ---------------- encoder fused super-step: warps split BY LAYER ----------------
// l0: warps 0-3 (kg2 x mw2), l1: 4-9 (kg3 x mw2), l2: 10-15 (kg3 x mw2).
// Each warp: full 16-j tile (8 W uint4 + 2 A uint4, 24 HMMA per k16).
__device__ __noinline__ void enc_superstep(
    float* sred, int tid, int s, int j0, int bt, int rp0, int rp1, int rp2)
{
    const int wid = tid>>5, lane = tid&31;
    int layer, wl, ltid, gsz, barid, kgN, sbase;
    if (wid < 4)      { layer=0; wl=wid;    ltid=tid;     gsz=128; barid=1; kgN=2; sbase=0; }
    else if (wid < 10){ layer=1; wl=wid-4;  ltid=tid-128; gsz=192; barid=2; kgN=3; sbase=2*2304; }
    else              { layer=2; wl=wid-10; ltid=tid-320; gsz=192; barid=3; kgN=3; sbase=5*2304; }
    const int kg = wl>>1, mw = wl&1;
    const int g = lane>>2, tig = lane&3;

    bool act; const uint4 *pA1, *pA2, *pW; int nk1, l; const float* bias; uint4* pHw;
    if (layer==0){
        act = (s < T_);
        pA1 = gXp + (size_t)s*2048; nk1 = 4;
        pA2 = &gPh[rp0][0][0]; pW = gWp[0]; bias = gBias[0]; l = 0;
        pHw = &gPh[rp0^1][0][0];
    } else if (layer==1){
        act = (s >= 1 && s < T_+1);
        pA1 = &gPh[rp0][0][0]; nk1 = 32;
        pA2 = &gPh[rp1][1][0]; pW = gWp[1]; bias = gBias[1]; l = 1;
        pHw = &gPh[rp1^1][1][0];
    } else {
        act = (s >= 2);
        pA1 = &gPh[rp1][1][0]; nk1 = 32;
        pA2 = &gPh[rp2][2][0]; pW = gWp[2]; bias = gBias[2]; l = 2;
        pHw = &gPh[rp2^1][2][0];
    }
    const int NK16 = nk1 + 32;
    const int mtile = bt*2 + mw;
    const int nb = j0>>3;

    float acc[4][2][4];
    #pragma unroll
    for (int q=0;q<4;q++)
        #pragma unroll
        for (int jj=0;jj<2;jj++)
            { acc[q][jj][0]=acc[q][jj][1]=acc[q][jj][2]=acc[q][jj][3]=0.f; }

    if (act){
        const uint4* wp[4][2];
        #pragma unroll
        for (int q=0;q<4;q++)
            #pragma unroll
            for (int jj=0;jj<2;jj++)
                wp[q][jj] = pW + ((size_t)(q*64 + nb + jj)*NK16 + kg)*32 + lane;
        auto aptr = [&](int i)->const uint4*{
            return (i<nk1) ? pA1 + (size_t)(mtile*nk1+i)*64 + lane
                           : pA2 + (size_t)(mtile*32 + (i-nk1))*64 + lane;
        };
        const int stepU = kgN*32;
        uint4 w[4][2], ahi, alo;
        { const uint4* ap = aptr(kg); ahi = ap[0]; alo = ap[32];
          #pragma unroll
          for (int q=0;q<4;q++)
              #pragma unroll
              for (int jj=0;jj<2;jj++) w[q][jj] = *wp[q][jj]; }

        for (int i = kg; i < NK16; i += kgN){
            uint4 nw[4][2], nahi, nalo;
            if (i + kgN < NK16){
                const uint4* ap = aptr(i+kgN); nahi = ap[0]; nalo = ap[32];
                #pragma unroll
                for (int q=0;q<4;q++)
                    #pragma unroll
                    for (int jj=0;jj<2;jj++) nw[q][jj] = wp[q][jj][stepU];
            }
            #pragma unroll
            for (int q=0;q<4;q++)
                #pragma unroll
                for (int jj=0;jj<2;jj++){
                    mma_bf16(acc[q][jj], ahi, w[q][jj].x, w[q][jj].y);
                    mma_bf16(acc[q][jj], ahi, w[q][jj].z, w[q][jj].w);
                    mma_bf16(acc[q][jj], alo, w[q][jj].x, w[q][jj].y);
                }
            #pragma unroll
            for (int q=0;q<4;q++)
                #pragma unroll
                for (int jj=0;jj<2;jj++) wp[q][jj] += stepU;
            ahi = nahi; alo = nalo;
            #pragma unroll
            for (int q=0;q<4;q++)
                #pragma unroll
                for (int jj=0;jj<2;jj++) w[q][jj] = nw[q][jj];
        }
        float* rg = sred + sbase + kg*2304;
        #pragma unroll
        for (int q=0;q<4;q++)
            #pragma unroll
            for (int jj=0;jj<2;jj++){
                float* t0 = rg + (q*16 + jj*8 + 2*tig)*36 + mw*16;
                t0[g] = acc[q][jj][0]; t0[g+8] = acc[q][jj][2];
                t0[36+g] = acc[q][jj][1]; t0[36+g+8] = acc[q][jj][3];
            }
    }
    asm volatile("bar.sync %0, %1;" :: "r"(barid), "r"(gsz) : "memory");
    if (act){
        for (int i = ltid; i < 512; i += gsz){
            int b_l = i>>4, j_l = i&15;
            float gate[4];
            #pragma unroll
            for (int q=0;q<4;q++){
                float ssum = 0.f;
                for (int kk=0; kk<kgN; kk++)
                    ssum += sred[sbase + kk*2304 + (q*16+j_l)*36 + b_l];
                gate[q] = ssum + bias[q*H_ + j0 + j_l];
            }
            cell_scatter(l, bt*32+b_l, j0+j_l, gate[0], gate[1], gate[2], gate[3],
                         pHw, false);
        }
    }
}

// ---------------- decoder layer-step (all 16 warps on one layer; 8-j tiles) ----
__device__ __noinline__ void layer_step(
    float* sred, int tid,
    const uint4* __restrict__ pA1, int nk1, const uint4* __restrict__ pA2,
    const uint4* __restrict__ pW, const float* __restrict__ bias,
    int l, uint4* __restrict__ pHw, int j0, int bt)
{
    const int wid = tid>>5, lane = tid&31;
    const int kg = wid>>2, sub = wid&3, mw = sub&1, jh = sub>>1;
    const int NK16 = nk1 + 32;
    const int mtile = bt*2 + mw;
    const int g = lane>>2, tig = lane&3;
    const int nb = (j0>>3) + jh;

    const uint4* wp0 = pW + ((size_t)(0*64 + nb)*NK16 + kg)*32 + lane;
    const uint4* wp1 = pW + ((size_t)(1*64 + nb)*NK16 + kg)*32 + lane;
    const uint4* wp2 = pW + ((size_t)(2*64 + nb)*NK16 + kg)*32 + lane;
    const uint4* wp3 = pW + ((size_t)(3*64 + nb)*NK16 + kg)*32 + lane;

    float acc[4][4];
    #pragma unroll
    for (int q = 0; q < 4; q++){ acc[q][0]=acc[q][1]=acc[q][2]=acc[q][3]=0.f; }

    auto aptr = [&](int i) -> const uint4* {
        return (i < nk1) ? pA1 + (size_t)(mtile*nk1 + i)*64 + lane
                         : pA2 + (size_t)(mtile*32 + (i-nk1))*64 + lane;
    };
    uint4 ahi, alo, w0, w1, w2, w3;
    { const uint4* ap = aptr(kg); ahi = ap[0]; alo = ap[32];
      w0 = *wp0; w1 = *wp1; w2 = *wp2; w3 = *wp3; }

    for (int i = kg; i < NK16; i += 4){
        uint4 nahi, nalo, nw0, nw1, nw2, nw3;
        if (i + 4 < NK16){
            const uint4* ap = aptr(i+4);
            nahi = ap[0]; nalo = ap[32];
            nw0 = wp0[128]; nw1 = wp1[128]; nw2 = wp2[128]; nw3 = wp3[128];
        }
        mma_bf16(acc[0], ahi, w0.x, w0.y);
        mma_bf16(acc[1], ahi, w1.x, w1.y);
        mma_bf16(acc[2], ahi, w2.x, w2.y);
        mma_bf16(acc[3], ahi, w3.x, w3.y);
        mma_bf16(acc[0], ahi, w0.z, w0.w);
        mma_bf16(acc[1], ahi, w1.z, w1.w);
        mma_bf16(acc[2], ahi, w2.z, w2.w);
        mma_bf16(acc[3], ahi, w3.z, w3.w);
        mma_bf16(acc[0], alo, w0.x, w0.y);
        mma_bf16(acc[1], alo, w1.x, w1.y);
        mma_bf16(acc[2], alo, w2.x, w2.y);
        mma_bf16(acc[3], alo, w3.x, w3.y);
        wp0 += 128; wp1 += 128; wp2 += 128; wp3 += 128;
        ahi = nahi; alo = nalo; w0 = nw0; w1 = nw1; w2 = nw2; w3 = nw3;
    }

    __syncthreads();
    {
        float* rg = sred + kg*2304;
        #pragma unroll
        for (int q = 0; q < 4; q++){
            float* t0 = rg + (q*16 + jh*8 + 2*tig)*36 + mw*16;
            t0[g] = acc[q][0]; t0[g+8] = acc[q][2];
            t0[36+g] = acc[q][1]; t0[36+g+8] = acc[q][3];
        }
    }
    __syncthreads();

    {
        const int b_l = tid>>4, j_l = tid&15;
        float gate[4];
        #pragma unroll
        for (int q = 0; q < 4; q++){
            float s = 0.f;
            #pragma unroll
            for (int kk = 0; kk < 4; kk++) s += sred[kk*2304 + (q*16+j_l)*36 + b_l];
            gate[q] = s + bias[q*H_ + j0 + j_l];
        }
        cell_scatter(l, bt*32+b_l, j0+j_l, gate[0], gate[1], gate[2], gate[3],
                     pHw, l == 2);
    }
}

__global__ __launch_bounds__(NTHR, 1) void lstm_persist(
    const float* __restrict__ x,
    const float* __restrict__ eWih0, const float* __restrict__ eWih,
    const float* __restrict__ eWhh,  const float* __restrict__ ebih,
    const float* __restrict__ ebhh,
    const float* __restrict__ dWih0, const float* __restrict__ dWih,
    const float* __restrict__ dWhh,  const float* __restrict__ dbih,
    const float* __restrict__ dbhh,
    const float* __restrict__ fcw,   const float* __restrict__ fcb,
    float* __restrict__ out)
{
    extern __shared__ char smemraw[];
    float* sred = (float*)smemraw;
    const int tid = threadIdx.x;
    const int bt = blockIdx.x >> 5;
    const int j0 = (blockIdx.x & 31)*16;
    const int grp = bt;
    const int gid = blockIdx.x*NTHR + tid;
    const size_t WS = (size_t)HG_*H_;

    // ---------------- init + packing ----------------
    for (int i = gid; i < 3*B_*H_; i += NTOT) (&g_c[0][0][0])[i] = 0.f;
    for (int i = gid; i < 2*3*16384; i += NTOT) (&gPh[0][0][0])[i] = make_uint4(0,0,0,0);
    {
        const float* bis[6] = {ebih, ebih+HG_, ebih+2*HG_, dbih, dbih+HG_, dbih+2*HG_};
        const float* bhs[6] = {ebhh, ebhh+HG_, ebhh+2*HG_, dbhh, dbhh+HG_, dbhh+2*HG_};
        for (int i = gid; i < 6*HG_; i += NTOT){
            int s = i >> 11, n = i & (HG_-1);
            gBias[s][n] = bis[s][n] + bhs[s][n];
        }
        for (int n = gid; n < HG_; n += NTOT){   // composed dec-l0 bias
            float cb = 0.f;
            #pragma unroll
            for (int f = 0; f < FOUT; f++) cb += dWih0[n*FOUT+f]*fcb[f];
            gBias[6][n] = dbih[n] + dbhh[n] + cb;
        }
    }
    if (gid < 256){   // seed decoder input x[:, FIN-1, 0:FOUT]
        int mt = gid>>5, lane = gid&31, g = lane>>2, tig = lane&3;
        unsigned short hv[8], lv[8];
        #pragma unroll
        for (int ri = 0; ri < 4; ri++){
            int r24 = ri>>1, a01 = ri&1;
            #pragma unroll
            for (int half = 0; half < 2; half++){
                int k = r24*8 + 2*tig + half;
                int b = mt*16 + a01*8 + g;
                float v = (k < FOUT) ? x[(size_t)b*(FIN*T_) + (size_t)(FIN-1)*T_ + k] : 0.f;
                bsplit(v, hv[ri*2+half], lv[ri*2+half]);
            }
        }
        gPp[mt*64 + lane]      = make_uint4(packu(hv[0],hv[1]),packu(hv[2],hv[3]),packu(hv[4],hv[5]),packu(hv[6],hv[7]));
        gPp[mt*64 + lane + 32] = make_uint4(packu(lv[0],lv[1]),packu(lv[2],lv[3]),packu(lv[4],lv[5]),packu(lv[6],lv[7]));
    }
    for (int idx = gid; idx < T_*8*4*32; idx += NTOT){   // pack x
        int lane = idx&31, k16 = (idx>>5)&3, mt = (idx>>7)&7, t = idx>>10;
        int g = lane>>2, tig = lane&3;
        int r0 = mt*16 + g, k0 = k16*16 + 2*tig;
        const float* xa = x + (size_t)r0*(FIN*T_) + t;
        const float* xb = x + (size_t)(r0+8)*(FIN*T_) + t;
        unsigned short h[8], l[8];
        bsplit(xa[(size_t)(k0  )*T_], h[0], l[0]); bsplit(xa[(size_t)(k0+1)*T_], h[1], l[1]);
        bsplit(xb[(size_t)(k0  )*T_], h[2], l[2]); bsplit(xb[(size_t)(k0+1)*T_], h[3], l[3]);
        bsplit(xa[(size_t)(k0+8)*T_], h[4], l[4]); bsplit(xa[(size_t)(k0+9)*T_], h[5], l[5]);
        bsplit(xb[(size_t)(k0+8)*T_], h[6], l[6]); bsplit(xb[(size_t)(k0+9)*T_], h[7], l[7]);
        size_t base = (size_t)((t*8 + mt)*4 + k16)*64 + lane;
        gXp[base]      = make_uint4(packu(h[0],h[1]),packu(h[2],h[3]),packu(h[4],h[5]),packu(h[6],h[7]));
        gXp[base + 32] = make_uint4(packu(l[0],l[1]),packu(l[2],l[3]),packu(l[4],l[5]),packu(l[6],l[7]));
    }
    {   // pack weights (set 3 = composed dec-l0: Wih0 @ fcw on k16<32)
        const float* W1s[6] = {eWih0, eWih, eWih+WS, dWih0, dWih, dWih+WS};
        const float* W2s[6] = {eWhh, eWhh+WS, eWhh+2*WS, dWhh, dWhh+WS, dWhh+2*WS};
        const int K1s[6]  = {64,512,512,512,512,512};
        const int nk1s[6] = {4,32,32,32,32,32};
        for (int s = 0; s < 6; s++){
            const float* W1 = W1s[s]; const float* W2 = W2s[s];
            const int K1 = K1s[s], nk1 = nk1s[s], NK16 = nk1+32;
            for (int idx = gid; idx < 256*NK16*32; idx += NTOT){
                int lane = idx&31, k16 = (idx>>5)%NK16, ntile = (idx>>5)/NK16;
                int g = lane>>2, tig = lane&3;
                int n = ntile*8 + g, kb = k16*16 + 2*tig;
                float v00,v01,v10,v11;
                if (k16 < nk1){
                    if (s == 3){   // composed: W(n,k) = sum_f dWih0[n,f]*fcw[f,k]
                        float a0=0,a1=0,a2=0,a3=0;
                        #pragma unroll
                        for (int f = 0; f < FOUT; f++){
                            float wv = dWih0[n*FOUT+f];
                            a0 += wv*fcw[f*H_+kb];   a1 += wv*fcw[f*H_+kb+1];
                            a2 += wv*fcw[f*H_+kb+8]; a3 += wv*fcw[f*H_+kb+9];
                        }
                        v00=a0; v01=a1; v10=a2; v11=a3;
                    } else {
                        v00 = (kb  <K1)? W1[(size_t)n*K1+kb]  :0.f;
                        v01 = (kb+1<K1)? W1[(size_t)n*K1+kb+1]:0.f;
                        v10 = (kb+8<K1)? W1[(size_t)n*K1+kb+8]:0.f;
                        v11 = (kb+9<K1)? W1[(size_t)n*K1+kb+9]:0.f;
                    }
                } else {
                    int k2 = kb - nk1*16;
                    v00 = W2[(size_t)n*H_+k2];   v01 = W2[(size_t)n*H_+k2+1];
                    v10 = W2[(size_t)n*H_+k2+8]; v11 = W2[(size_t)n*H_+k2+9];
                }
                unsigned short h00,l00,h01,l01,h10,l10,h11,l11;
                bsplit(v00,h00,l00); bsplit(v01,h01,l01);
                bsplit(v10,h10,l10); bsplit(v11,h11,l11);
                gWp[s][idx] = make_uint4(packu(h00,h01),packu(h10,h11),packu(l00,l01),packu(l10,l11));
            }
        }
        // original dec-l0 (seed step): NK16=33, nk1=1, K1=8
        for (int idx = gid; idx < 256*33*32; idx += NTOT){
            int lane = idx&31, k16 = (idx>>5)%33, ntile = (idx>>5)/33;
            int g = lane>>2, tig = lane&3;
            int n = ntile*8 + g, kb = k16*16 + 2*tig;
            float v00,v01,v10,v11;
            if (k16 < 1){
                v00 = (kb  <FOUT)? dWih0[(size_t)n*FOUT+kb]  :0.f;
                v01 = (kb+1<FOUT)? dWih0[(size_t)n*FOUT+kb+1]:0.f;
                v10 = 0.f; v11 = 0.f;
            } else {
                int k2 = kb - 16;
                v00 = dWhh[(size_t)n*H_+k2];   v01 = dWhh[(size_t)n*H_+k2+1];
                v10 = dWhh[(size_t)n*H_+k2+8]; v11 = dWhh[(size_t)n*H_+k2+9];
            }
            unsigned short h00,l00,h01,l01,h10,l10,h11,l11;
            bsplit(v00,h00,l00); bsplit(v01,h01,l01);
            bsplit(v10,h10,l10); bsplit(v11,h11,l11);
            gWp0d[idx] = make_uint4(packu(h00,h01),packu(h10,h11),packu(l00,l01),packu(l10,l11));
        }
    }
    grid_barrier();

    // -------- encoder: layer-PARALLEL wavefront, 1 barrier / super-step --------
    int rp0 = 0, rp1 = 0, rp2 = 0;
    for (int s = 0; s < T_ + 2; ++s){
        enc_superstep(sred, tid, s, j0, bt, rp0, rp1, rp2);
        if (s < T_) rp0 ^= 1;
        if (s >= 1 && s < T_+1) rp1 ^= 1;
        if (s >= 2) rp2 ^= 1;
        group_barrier(grp);
    }

    // -------- decoder: 3 barrier rounds/step (FC composed into l0) --------
    for (int d = 0; d < WOUT; ++d){
        if (d == 0)
            layer_step(sred, tid, gPp, 1, &gPh[rp0][0][0],
                       gWp0d, gBias[3], 0, &gPh[rp0^1][0][0], j0, bt);
        else
            layer_step(sred, tid, &gPh[rp2][2][0], 32, &gPh[rp0][0][0],
                       gWp[3], gBias[6], 0, &gPh[rp0^1][0][0], j0, bt);
        rp0 ^= 1; group_barrier(grp);
        layer_step(sred, tid, &gPh[rp0][0][0], 32, &gPh[rp1][1][0],
                   gWp[4], gBias[4], 1, &gPh[rp1^1][1][0], j0, bt);
        rp1 ^= 1; group_barrier(grp);
        layer_step(sred, tid, &gPh[rp1][1][0], 32, &gPh[rp2][2][0],
                   gWp[5], gBias[5], 2, &gPh[rp2^1][2][0], j0, bt);
        rp2 ^= 1; group_barrier(grp);
        // FC output (off critical path; h2 published by the barrier above)
        if (tid < 256){
            int f = tid>>5, lnn = tid&31, b = blockIdx.x;
            const float* hrow = &g_h[2][b][0];
            const float* wrow = fcw + f*H_;
            float ssum = 0.f;
            #pragma unroll 4
            for (int j = lnn; j < H_; j += 32) ssum += hrow[j]*wrow[j];
            #pragma unroll
            for (int o = 16; o; o >>= 1) ssum += __shfl_down_sync(0xffffffffu, ssum, o);
            if (lnn == 0)
                out[(size_t)b*(FOUT*WOUT) + f*WOUT + d] = ssum + fcb[f];
        }
    }
}

extern "C" void kernel_launch(void* const* d_in, const int* in_sizes, int n_in,
                              void* d_out, int out_size)
{
    cudaFuncSetAttribute(lstm_persist,
                         cudaFuncAttributeMaxDynamicSharedMemorySize, SRED_BYTES);
    lstm_persist<<<NCTA, NTHR, SRED_BYTES>>>(
        (const float*)d_in[0], (const float*)d_in[1], (const float*)d_in[2],
        (const float*)d_in[3], (const float*)d_in[4], (const float*)d_in[5],
        (const float*)d_in[6], (const float*)d_in[7], (const float*)d_in[8],
        (const float*)d_in[9], (const float*)d_in[10], (const float*)d_in[11],
        (const float*)d_in[12], (float*)d_out);
}